// round 5
// baseline (speedup 1.0000x reference)
#include <cuda_runtime.h>
#include <cstdint>

#define NB    32
#define NS    1024
#define ROWS  (NB * NS)      // 32768
#define KNN   32
#define NIN   64             // 2*K
#define MID   32
#define HALF_K 32            // k-range per lane of a pair
#define PAD   4              // 16B pad between weight halves (bank shift)

// packed f32x2 ops (sm_100+)
__device__ __forceinline__ unsigned long long fma2(unsigned long long a,
                                                   unsigned long long b,
                                                   unsigned long long c) {
    unsigned long long d;
    asm("fma.rn.f32x2 %0, %1, %2, %3;" : "=l"(d) : "l"(a), "l"(b), "l"(c));
    return d;
}
__device__ __forceinline__ unsigned long long add2(unsigned long long a,
                                                   unsigned long long b) {
    unsigned long long d;
    asm("add.rn.f32x2 %0, %1, %2;" : "=l"(d) : "l"(a), "l"(b));
    return d;
}
__device__ __forceinline__ unsigned long long pack2(float lo, float hi) {
    unsigned long long d;
    asm("mov.b64 %0, {%1, %2};" : "=l"(d) : "f"(lo), "f"(hi));
    return d;
}
__device__ __forceinline__ void unpack2(unsigned long long v, float& lo, float& hi) {
    asm("mov.b64 {%0, %1}, %2;" : "=f"(lo), "=f"(hi) : "l"(v));
}

// tanh(x) = 1 - 2/(exp(2x)+1) via ex2.approx + rcp.approx (~1e-6 rel err)
__device__ __forceinline__ float fast_tanh(float x) {
    float e, r;
    asm("ex2.approx.f32 %0, %1;" : "=f"(e) : "f"(x * 2.8853900817779268f));
    asm("rcp.approx.f32 %0, %1;" : "=f"(r) : "f"(e + 1.0f));
    return fmaf(-2.0f, r, 1.0f);
}

__global__ __launch_bounds__(128, 1)
void metak_kernel(const int*   __restrict__ vals,
                  const float* __restrict__ dist,
                  const float* __restrict__ fc2_w1,   // [64,32]
                  const float* __restrict__ fc2_b1,   // [32]
                  const float* __restrict__ fc2_w2,   // [32,2]
                  const float* __restrict__ fc2_b2,   // [2]
                  const float* __restrict__ fc1_w1,   // [2,4]
                  const float* __restrict__ fc1_b1,   // [4]
                  const float* __restrict__ fc1_w2,   // [4,1]
                  const float* __restrict__ fc1_b2,   // [1]
                  float*       __restrict__ out)
{
    // weight rows 0..31 at [0 .. 1024), rows 32..63 at [1028 .. 2052): 16B pad
    __shared__ __align__(16) float sw1[2 * HALF_K * MID + PAD];
    __shared__ float sb1[MID];
    __shared__ float sw2[MID * 2];
    __shared__ float sb2[2];
    __shared__ float sf1w1[8];
    __shared__ float sf1b1[4];
    __shared__ float sf1w2[4];
    __shared__ float sf1b2;

    const int tid = threadIdx.x;
    for (int i = tid; i < NIN * MID; i += blockDim.x) {
        int dst = (i < HALF_K * MID) ? i : (i + PAD);
        sw1[dst] = fc2_w1[i];
    }
    if (tid < MID)     sb1[tid]   = fc2_b1[tid];
    if (tid < MID * 2) sw2[tid]   = fc2_w2[tid];
    if (tid < 2)       sb2[tid]   = fc2_b2[tid];
    if (tid < 8)       sf1w1[tid] = fc1_w1[tid];
    if (tid < 4)       sf1b1[tid] = fc1_b1[tid];
    if (tid < 4)       sf1w2[tid] = fc1_w2[tid];
    if (tid == 0)      sf1b2      = fc1_b2[0];
    __syncthreads();

    const int gt     = blockIdx.x * blockDim.x + tid;   // 2 threads per row
    const int row    = gt >> 1;
    const int parity = gt & 1;                          // 0: distances, 1: labels

    // ---- batched global loads: 8 x LDG.128, MLP=8 ----
    const int4* p = parity ? (reinterpret_cast<const int4*>(vals) + (size_t)row * 8)
                           : (reinterpret_cast<const int4*>(dist) + (size_t)row * 8);
    int4 r0 = p[0], r1 = p[1], r2 = p[2], r3 = p[3],
         r4 = p[4], r5 = p[5], r6 = p[6], r7 = p[7];

    int rv[HALF_K];
    rv[0]=r0.x; rv[1]=r0.y; rv[2]=r0.z; rv[3]=r0.w;
    rv[4]=r1.x; rv[5]=r1.y; rv[6]=r1.z; rv[7]=r1.w;
    rv[8]=r2.x; rv[9]=r2.y; rv[10]=r2.z; rv[11]=r2.w;
    rv[12]=r3.x; rv[13]=r3.y; rv[14]=r3.z; rv[15]=r3.w;
    rv[16]=r4.x; rv[17]=r4.y; rv[18]=r4.z; rv[19]=r4.w;
    rv[20]=r5.x; rv[21]=r5.y; rv[22]=r5.z; rv[23]=r5.w;
    rv[24]=r6.x; rv[25]=r6.y; rv[26]=r6.z; rv[27]=r6.w;
    rv[28]=r7.x; rv[29]=r7.y; rv[30]=r7.z; rv[31]=r7.w;

    // ---- build x[32]: distances (even) or prefix distinct-nonzero counts (odd) ----
    float x[HALF_K];
    if (parity) {
        // labels in [0,100); bit 0 of m0 pre-set so label 0 never counts
        unsigned long long m0 = 1ull, m1 = 0ull;
        int cnt = 0;
#pragma unroll
        for (int i = 0; i < HALF_K; i++) {
            int v = rv[i];
            unsigned long long bit = 1ull << (v & 63);
            bool hi = (v & 64) != 0;
            unsigned long long cur = hi ? m1 : m0;
            cnt += (int)((cur & bit) == 0ull);
            cur |= bit;
            if (hi) m1 = cur; else m0 = cur;
            x[i] = (float)cnt;
        }
    } else {
#pragma unroll
        for (int i = 0; i < HALF_K; i++) x[i] = __int_as_float(rv[i]);
    }

    // ---- half-GEMV: 32 k-values x 32 outputs, warp-uniform ----
    const float* swp = sw1 + parity * (HALF_K * MID + PAD);

    unsigned long long acc[MID / 2];
    if (parity) {
#pragma unroll
        for (int j = 0; j < MID / 2; j++) acc[j] = 0ull;
    } else {
#pragma unroll
        for (int j = 0; j < MID / 2; j++) acc[j] = pack2(sb1[2*j], sb1[2*j+1]);
    }

#pragma unroll
    for (int k = 0; k < HALF_K; k++) {
        unsigned long long xp = pack2(x[k], x[k]);
        const ulonglong2* wrow = reinterpret_cast<const ulonglong2*>(swp + k * MID);
#pragma unroll
        for (int q = 0; q < 8; q++) {
            ulonglong2 w = wrow[q];
            acc[2*q]   = fma2(xp, w.x, acc[2*q]);
            acc[2*q+1] = fma2(xp, w.y, acc[2*q+1]);
        }
    }

    // ---- pair exchange: each lane ends up owning 16 hidden units ----
    // even lane -> h[0..15]  (its acc[0..7]  + odd's acc[0..7])
    // odd  lane -> h[16..31] (its acc[8..15] + even's acc[8..15])
#pragma unroll
    for (int j = 0; j < 8; j++) {
        unsigned long long send = parity ? acc[j] : acc[8 + j];
        unsigned long long recv = __shfl_xor_sync(0xffffffffu, send, 1);
        if (parity) acc[8 + j] = add2(acc[8 + j], recv);
        else        acc[j]     = add2(acc[j],     recv);
    }

    // ---- tanh + partial fc2 layer 2 over own 16 hidden units ----
    const int hbase = parity * 16;           // h index offset
    const int abase = parity * 8;            // acc index offset
    float o0 = 0.f, o1 = 0.f;
#pragma unroll
    for (int j = 0; j < 8; j++) {
        float a, b;
        unpack2(acc[abase + j], a, b);
        float ha = fast_tanh(a);
        float hb = fast_tanh(b);
        int h0 = hbase + 2*j, h1 = hbase + 2*j + 1;
        o0 = fmaf(ha, sw2[2*h0],   o0);
        o1 = fmaf(ha, sw2[2*h0+1], o1);
        o0 = fmaf(hb, sw2[2*h1],   o0);
        o1 = fmaf(hb, sw2[2*h1+1], o1);
    }
    o0 += __shfl_xor_sync(0xffffffffu, o0, 1);
    o1 += __shfl_xor_sync(0xffffffffu, o1, 1);

    if (!parity) {
        o0 += sb2[0];
        o1 += sb2[1];
        float r = sf1b2;
#pragma unroll
        for (int c = 0; c < 4; c++) {
            float t = fast_tanh(fmaf(o1, sf1w1[4 + c], fmaf(o0, sf1w1[c], sf1b1[c])));
            r = fmaf(t, sf1w2[c], r);
        }
        float* op = out + (size_t)row * 3;
        op[0] = o0;
        op[1] = o1;
        op[2] = r;
    }
}

extern "C" void kernel_launch(void* const* d_in, const int* in_sizes, int n_in,
                              void* d_out, int out_size)
{
    const int*   vals   = (const int*)  d_in[0];
    const float* dist   = (const float*)d_in[1];
    const float* fc2_w1 = (const float*)d_in[2];
    const float* fc2_b1 = (const float*)d_in[3];
    const float* fc2_w2 = (const float*)d_in[4];
    const float* fc2_b2 = (const float*)d_in[5];
    const float* fc1_w1 = (const float*)d_in[6];
    const float* fc1_b1 = (const float*)d_in[7];
    const float* fc1_w2 = (const float*)d_in[8];
    const float* fc1_b2 = (const float*)d_in[9];
    float* out = (float*)d_out;

    const int threads = 128;
    const int blocks  = (ROWS * 2) / threads;  // 512 blocks
    metak_kernel<<<blocks, threads>>>(vals, dist,
                                      fc2_w1, fc2_b1, fc2_w2, fc2_b2,
                                      fc1_w1, fc1_b1, fc1_w2, fc1_b2,
                                      out);
}